// round 2
// baseline (speedup 1.0000x reference)
#include <cuda_runtime.h>

#define B_ROWS 16384
#define NN     128
#define NS     1024
#define GRID_MAIN 444            // 3 blocks/SM * 148 SMs, single wave
#define BLOCK_MAIN 256
#define LANES (GRID_MAIN * 2)

// ---------------- scratch (device globals; statically zero-initialized) ----------------
// Invariant: zero at entry of every kernel_launch call; the finalizing block
// resets everything it consumed, so graph replays keep the invariant.
__device__ float g_nP[NN];      // sum y*softplus(x)   (narrative)
__device__ float g_nR[NN];      // sum y*x
__device__ float g_nC[NN];      // sum y
__device__ float g_sP[NS];      // sum g*s*softplus(x) (sub)
__device__ float g_sR[NS];      // sum g*s*x
__device__ float g_sC[NS];      // sum s  (ungated column count)
__device__ float g_scl[8];      // 0=Qt (sum g*spx_sub), 1=Tt (sum spx_narr), 2=hier, 3=nf, 4=sf
__device__ unsigned int g_ctr;

__device__ __forceinline__ float softplus_f(float x) {
    // softplus(x) = max(x,0) + log1p(exp(-|x|)); 2 MUFU (EX2, LG2)
    float e = exp2f(-1.4426950408889634f * fabsf(x));
    float L = 0.6931471805599453f * __log2f(1.0f + e);
    return fmaxf(x, 0.0f) + L;
}

__global__ __launch_bounds__(BLOCK_MAIN, 3)
void fused_kernel(const float* __restrict__ nlg, const float* __restrict__ slg,
                  const int* __restrict__ nlb,  const int* __restrict__ slb,
                  float* __restrict__ out)
{
    const int tid  = threadIdx.x;
    const int n    = tid & 127;                     // narrative class owned
    const int lane = blockIdx.x * 2 + (tid >> 7);   // row-processor id

    float Pn = 0.f, Rn = 0.f;
    float P[8], R[8];
#pragma unroll
    for (int k = 0; k < 8; k++) { P[k] = 0.f; R[k] = 0.f; }
    float Qt = 0.f, Tt = 0.f, hier = 0.f, nf = 0.f, sf = 0.f;
    int cn = 0, ca = 0, cb = 0;   // packed byte-lane counts (max ~19 per lane, no overflow)

    const float4* sp  = (const float4*)slg + (size_t)lane * (NS / 4) + n * 2;
    const int4*   slp = (const int4*)slb   + (size_t)lane * (NS / 4) + n * 2;
    const float*  np  = nlg + (size_t)lane * NN + n;
    const int*    nbp = nlb + (size_t)lane * NN + n;
    const size_t  sstep = (size_t)LANES * (NS / 4);
    const size_t  nstep = (size_t)LANES * NN;

    for (int r = lane; r < B_ROWS; r += LANES) {
        float xn = *np;
        int   gi = *nbp;
        float4 v0 = sp[0];
        float4 v1 = sp[1];
        int4   l0 = slp[0];
        int4   l1 = slp[1];
        sp += sstep; slp += sstep; np += nstep; nbp += nstep;

        float g = (float)gi;

        // ---- narrative element ----
        float spn = softplus_f(xn);
        float dn  = xn - spn;                          // = log sigmoid(xn)
        float wn  = exp2f(-2.8853900817779268f * spn); // (1-sigmoid)^2
        nf = fmaf(g * wn, dn, nf);
        Pn = fmaf(g, spn, Pn);
        Rn = fmaf(g, xn, Rn);
        Tt += spn;
        cn += gi;
        float pn = exp2f(1.4426950408889634f * dn);    // sigmoid(xn)

        // ---- 8 subnarrative elements of this group ----
        float xs[8] = { v0.x, v0.y, v0.z, v0.w, v1.x, v1.y, v1.z, v1.w };
        int   li[8] = { l0.x, l0.y, l0.z, l0.w, l1.x, l1.y, l1.z, l1.w };
        float mx = xs[0];
#pragma unroll
        for (int k = 0; k < 8; k++) {
            float x   = xs[k];
            float s   = (float)li[k];
            float spx = softplus_f(x);
            float d   = x - spx;
            float w   = exp2f(-2.8853900817779268f * spx);
            sf   = fmaf(s * w, d, sf);
            float gs = g * s;
            P[k] = fmaf(gs, spx, P[k]);
            R[k] = fmaf(gs, x,   R[k]);
            Qt   = fmaf(g,  spx, Qt);
            mx   = fmaxf(mx, x);
        }
        ca += li[0] + (li[1] << 8) + (li[2] << 16) + (li[3] << 24);
        cb += li[4] + (li[5] << 8) + (li[6] << 16) + (li[7] << 24);

        // ---- hierarchy: max(sigmoid)=sigmoid(max); relu handles ordering ----
        float em = exp2f(-1.4426950408889634f * mx);
        float pm = __fdividef(1.0f, 1.0f + em);
        hier = fmaf(g, fmaxf(pm - pn, 0.0f), hier);
    }

    // ---------------- pair the two 128-lane halves in shared ----------------
    __shared__ float sh[128][27];    // stride 27 (odd) -> conflict-free
    if (tid >= 128) {
        float* d = sh[tid - 128];
        d[0] = Pn; d[1] = Rn;
#pragma unroll
        for (int k = 0; k < 8; k++) { d[2 + k] = P[k]; d[10 + k] = R[k]; }
        d[18] = Qt; d[19] = Tt; d[20] = hier; d[21] = nf; d[22] = sf;
        d[23] = __int_as_float(cn); d[24] = __int_as_float(ca); d[25] = __int_as_float(cb);
    }
    __syncthreads();

    if (tid < 128) {
        float* d = sh[tid];
        Pn += d[0]; Rn += d[1];
#pragma unroll
        for (int k = 0; k < 8; k++) { P[k] += d[2 + k]; R[k] += d[10 + k]; }
        Qt += d[18]; Tt += d[19]; hier += d[20]; nf += d[21]; sf += d[22];
        cn += __float_as_int(d[23]);
        ca += __float_as_int(d[24]);
        cb += __float_as_int(d[25]);

        atomicAdd(&g_nP[n], Pn);
        atomicAdd(&g_nR[n], Rn);
        atomicAdd(&g_nC[n], (float)cn);
#pragma unroll
        for (int k = 0; k < 8; k++) {
            atomicAdd(&g_sP[n * 8 + k], P[k]);
            atomicAdd(&g_sR[n * 8 + k], R[k]);
        }
#pragma unroll
        for (int k = 0; k < 4; k++) {
            atomicAdd(&g_sC[n * 8 + k],     (float)((ca >> (8 * k)) & 255));
            atomicAdd(&g_sC[n * 8 + 4 + k], (float)((cb >> (8 * k)) & 255));
        }
    }

    // scalar block-reduce over lower 128 threads (4 full warps)
    __shared__ float sw[5][4];
    if (tid < 128) {
#pragma unroll
        for (int o = 16; o; o >>= 1) {
            Qt   += __shfl_down_sync(0xffffffffu, Qt,   o);
            Tt   += __shfl_down_sync(0xffffffffu, Tt,   o);
            hier += __shfl_down_sync(0xffffffffu, hier, o);
            nf   += __shfl_down_sync(0xffffffffu, nf,   o);
            sf   += __shfl_down_sync(0xffffffffu, sf,   o);
        }
        if ((tid & 31) == 0) {
            int w = tid >> 5;
            sw[0][w] = Qt; sw[1][w] = Tt; sw[2][w] = hier; sw[3][w] = nf; sw[4][w] = sf;
        }
    }
    __syncthreads();
    if (tid == 0) {
        atomicAdd(&g_scl[0], sw[0][0] + sw[0][1] + sw[0][2] + sw[0][3]);
        atomicAdd(&g_scl[1], sw[1][0] + sw[1][1] + sw[1][2] + sw[1][3]);
        atomicAdd(&g_scl[2], sw[2][0] + sw[2][1] + sw[2][2] + sw[2][3]);
        atomicAdd(&g_scl[3], sw[3][0] + sw[3][1] + sw[3][2] + sw[3][3]);
        atomicAdd(&g_scl[4], sw[4][0] + sw[4][1] + sw[4][2] + sw[4][3]);
    }

    // ---------------- last block finalizes and resets scratch ----------------
    __threadfence();
    __shared__ unsigned int s_last;
    if (tid == 0) s_last = (atomicAdd(&g_ctr, 1u) == (unsigned)(gridDim.x - 1)) ? 1u : 0u;
    __syncthreads();
    if (!s_last) return;
    __threadfence();

    double subAcc = 0.0, narrAcc = 0.0, valid = 0.0;
    for (int c = tid; c < NS; c += BLOCK_MAIN) {
        float Pv = g_sP[c], Rv = g_sR[c], Cv = g_sC[c];
        float pw = fminf(fmaxf((16384.0f - Cv) / (Cv + 1e-6f), 1.0f), 50.0f);
        subAcc += (double)pw * (double)(Pv - Rv) - (double)Pv;
    }
    for (int c = tid; c < NN; c += BLOCK_MAIN) {
        float Pv = g_nP[c], Rv = g_nR[c], Cv = g_nC[c];
        float pw = fminf(fmaxf((16384.0f - Cv) / (Cv + 1e-6f), 1.0f), 50.0f);
        narrAcc += (double)pw * (double)(Pv - Rv) - (double)Pv;
        valid   += (double)Cv;
    }
#pragma unroll
    for (int o = 16; o; o >>= 1) {
        subAcc  += __shfl_down_sync(0xffffffffu, subAcc,  o);
        narrAcc += __shfl_down_sync(0xffffffffu, narrAcc, o);
        valid   += __shfl_down_sync(0xffffffffu, valid,   o);
    }
    __shared__ double rd[24];
    if ((tid & 31) == 0) {
        int w = tid >> 5;   // 8 warps
        rd[w] = subAcc; rd[8 + w] = narrAcc; rd[16 + w] = valid;
    }
    __syncthreads();
    if (tid == 0) {
        double ss = 0.0, ns = 0.0, vv = 0.0;
        for (int i = 0; i < 8; i++) { ss += rd[i]; ns += rd[8 + i]; vv += rd[16 + i]; }
        double Qts = g_scl[0], Tts = g_scl[1], hs = g_scl[2], nfs = g_scl[3], sfs = g_scl[4];

        double narrative_loss = (ns + Tts) / (16384.0 * 128.0);
        double sub_loss = (vv > 0.0) ? ((ss + Qts) / 8.0) / fmax(vv, 1.0) : 0.0;
        double total = (narrative_loss - 0.1 * nfs / (16384.0 * 128.0))
                     + (sub_loss       - 0.1 * sfs / (16384.0 * 1024.0))
                     + 0.5 * hs / 16384.0;
        out[0] = (float)total;
    }
    __syncthreads();

    // reset scratch for the next graph replay
    for (int i = tid; i < NS; i += BLOCK_MAIN) { g_sP[i] = 0.f; g_sR[i] = 0.f; g_sC[i] = 0.f; }
    for (int i = tid; i < NN; i += BLOCK_MAIN) { g_nP[i] = 0.f; g_nR[i] = 0.f; g_nC[i] = 0.f; }
    if (tid < 8) g_scl[tid] = 0.f;
    if (tid == 0) g_ctr = 0u;
}

extern "C" void kernel_launch(void* const* d_in, const int* in_sizes, int n_in,
                              void* d_out, int out_size)
{
    const float* nlg = (const float*)d_in[0];   // narrative_logits [B,128]
    const float* slg = (const float*)d_in[1];   // subnarrative_logits [B,1024]
    const int*   nlb = (const int*)d_in[2];     // narrative_labels [B,128]
    const int*   slb = (const int*)d_in[3];     // subnarrative_labels [B,1024]
    (void)in_sizes; (void)n_in; (void)out_size;

    fused_kernel<<<GRID_MAIN, BLOCK_MAIN>>>(nlg, slg, nlb, slb, (float*)d_out);
}